// round 17
// baseline (speedup 1.0000x reference)
#include <cuda_runtime.h>

#define SEQ     2048
#define HEADS   8
#define TILE_I  128
#define MI      2                  // queries per thread
#define SLOTS   (TILE_I / MI)      // 64 query slots
#define JG      16                 // lanes per slot (j-groups)
#define NTHREADS (SLOTS * JG)      // 1024
#define JPAIRS  (SEQ / 2)          // 1024 packed j-pairs

using u64 = unsigned long long;

__device__ __forceinline__ u64 pack2(float lo, float hi) {
    u64 r; asm("mov.b64 %0, {%1, %2};" : "=l"(r) : "f"(lo), "f"(hi)); return r;
}
__device__ __forceinline__ void unpack2(u64 v, float& lo, float& hi) {
    asm("mov.b64 {%0, %1}, %2;" : "=f"(lo), "=f"(hi) : "l"(v));
}
__device__ __forceinline__ u64 fma2(u64 a, u64 b, u64 c) {
    u64 d; asm("fma.rn.f32x2 %0, %1, %2, %3;" : "=l"(d) : "l"(a), "l"(b), "l"(c)); return d;
}
__device__ __forceinline__ u64 mul2(u64 a, u64 b) {
    u64 d; asm("mul.rn.f32x2 %0, %1, %2;" : "=l"(d) : "l"(a), "l"(b)); return d;
}
__device__ __forceinline__ u64 add2(u64 a, u64 b) {
    u64 d; asm("add.rn.f32x2 %0, %1, %2;" : "=l"(d) : "l"(a), "l"(b)); return d;
}

// exp(2s) for s in [-0.354, 0.354], entirely on the fma pipe (packed f32x2):
// u = Taylor5(e^s), p = u*u. Rel err ~5e-6.
__device__ __forceinline__ u64 exp2s(u64 s, u64 C5, u64 C4, u64 C3, u64 C2,
                                     u64 C1, u64 C0) {
    u64 u = fma2(C5, s, C4);
    u = fma2(u, s, C3);
    u = fma2(u, s, C2);
    u = fma2(u, s, C1);
    u = fma2(u, s, C0);
    return mul2(u, u);
}

// SoA, j-pair packed: one 8B word = component of keys (2jp, 2jp+1).
// LDS.64 by 16 distinct words, duplicated across warp halves -> 1 crossbar
// wavefront per load (LDS.128 variant measured WORSE: 4 wf/load).
// 6 * 8KB = 48KB static smem.
__shared__ float2 s_kx[JPAIRS];
__shared__ float2 s_ky[JPAIRS];
__shared__ float2 s_kz[JPAIRS];
__shared__ float2 s_kw[JPAIRS];
__shared__ float2 s_v0[JPAIRS];
__shared__ float2 s_v1[JPAIRS];

__global__ __launch_bounds__(NTHREADS, 1)
void su2_attn_kernel(const float* __restrict__ re,
                     const float* __restrict__ im,
                     float* __restrict__ out) {
    const int h   = blockIdx.y;
    const int tid = threadIdx.x;

    float* kx = reinterpret_cast<float*>(s_kx);
    float* ky = reinterpret_cast<float*>(s_ky);
    float* kz = reinterpret_cast<float*>(s_kz);
    float* kw = reinterpret_cast<float*>(s_kw);
    float* v0 = reinterpret_cast<float*>(s_v0);
    float* v1 = reinterpret_cast<float*>(s_v1);

    // Phase 1: normalize all 2048 keys of this head into smem (SoA).
    #pragma unroll
    for (int j = tid; j < SEQ; j += NTHREADS) {
        const int base = j * (HEADS * 2) + h * 2;
        const float2 r = *reinterpret_cast<const float2*>(re + base);
        const float2 m = *reinterpret_cast<const float2*>(im + base);
        const float ss  = r.x * r.x + r.y * r.y + m.x * m.x + m.y * m.y;
        const float rin = rsqrtf(ss);
        kx[j] = r.x * rin;
        ky[j] = r.y * rin;
        kz[j] = m.x * rin;
        kw[j] = m.y * rin;
        v0[j] = r.x;          // raw = unnormalized V (real part, dim 0)
        v1[j] = r.y;          // raw = unnormalized V (real part, dim 1)
    }
    __syncthreads();

    const int slot  = tid >> 4;      // 0..63
    const int jg    = tid & 15;      // 0..15, adjacent lanes in warp
    const int ibase = blockIdx.x * TILE_I + slot;

    // Half-argument: q scaled by 0.5*SCALE so s = dot in [-0.354, 0.354],
    // exp(dot*SCALE) = (e^s)^2. Logits bounded by unit vectors -> softmax
    // needs no max subtraction.
    const float C = 0.5f * 0.70710678118654752f;

    // Taylor deg-5 coefficients for e^s (packed broadcast).
    const u64 C5 = pack2(8.3333333e-3f, 8.3333333e-3f);
    const u64 C4 = pack2(4.1666668e-2f, 4.1666668e-2f);
    const u64 C3 = pack2(1.6666667e-1f, 1.6666667e-1f);
    const u64 C2 = pack2(0.5f, 0.5f);
    const u64 C1 = pack2(1.0f, 1.0f);
    const u64 C0 = pack2(1.0f, 1.0f);

    // Broadcast-packed query constants (MI=2 queries per thread).
    u64 qx[MI], qy[MI], qz[MI], qw[MI];
    #pragma unroll
    for (int q = 0; q < MI; q++) {
        const int i = ibase + q * SLOTS;
        float vx = kx[i] * C, vy = ky[i] * C, vz = kz[i] * C, vw = kw[i] * C;
        qx[q] = pack2(vx, vx);
        qy[q] = pack2(vy, vy);
        qz[q] = pack2(vz, vz);
        qw[q] = pack2(vw, vw);
    }

    u64 lacc[MI], a0[MI], a1[MI];
    #pragma unroll
    for (int q = 0; q < MI; q++) { lacc[q] = 0ull; a0[q] = 0ull; a1[q] = 0ull; }

    #pragma unroll 4
    for (int jp = jg; jp < JPAIRS; jp += JG) {
        const u64 kx01 = *reinterpret_cast<const u64*>(&s_kx[jp]);
        const u64 ky01 = *reinterpret_cast<const u64*>(&s_ky[jp]);
        const u64 kz01 = *reinterpret_cast<const u64*>(&s_kz[jp]);
        const u64 kw01 = *reinterpret_cast<const u64*>(&s_kw[jp]);
        const u64 v001 = *reinterpret_cast<const u64*>(&s_v0[jp]);
        const u64 v101 = *reinterpret_cast<const u64*>(&s_v1[jp]);
        #pragma unroll
        for (int q = 0; q < MI; q++) {
            u64 s = mul2(qw[q], kw01);
            s = fma2(qz[q], kz01, s);
            s = fma2(qy[q], ky01, s);
            s = fma2(qx[q], kx01, s);
            const u64 p = exp2s(s, C5, C4, C3, C2, C1, C0); // exp(dot*SCALE)
            lacc[q] = add2(lacc[q], p);
            a0[q] = fma2(p, v001, a0[q]);    // out real, spinor dim 0
            a1[q] = fma2(p, v101, a1[q]);    // out real, spinor dim 1
        }
    }

    // Collapse pairs -> scalars, then butterfly-reduce the 16 j-group lanes.
    #pragma unroll
    for (int q = 0; q < MI; q++) {
        float llo, lhi, xlo, xhi, ylo, yhi;
        unpack2(lacc[q], llo, lhi);
        unpack2(a0[q],  xlo, xhi);
        unpack2(a1[q],  ylo, yhi);
        float l = llo + lhi, x = xlo + xhi, y = ylo + yhi;
        #pragma unroll
        for (int m = 1; m <= 8; m <<= 1) {
            l += __shfl_xor_sync(0xffffffffu, l, m);
            x += __shfl_xor_sync(0xffffffffu, x, m);
            y += __shfl_xor_sync(0xffffffffu, y, m);
        }
        if (jg == 0) {
            const int i = ibase + q * SLOTS;
            const float inv = 1.0f / l;
            // real-part-only output, float32 (1,2048,8,2): offset i*16 + h*2 + d
            reinterpret_cast<float2*>(out)[i * HEADS + h] = make_float2(x * inv, y * inv);
        }
    }
}

extern "C" void kernel_launch(void* const* d_in, const int* in_sizes, int n_in,
                              void* d_out, int out_size) {
    const float* re = (const float*)d_in[0];
    const float* im = (const float*)d_in[1];
    float* out = (float*)d_out;

    dim3 grid(SEQ / TILE_I, HEADS);
    su2_attn_kernel<<<grid, NTHREADS>>>(re, im, out);
}